// round 8
// baseline (speedup 1.0000x reference)
#include <cuda_runtime.h>

#define HDIM 50
#define TLEN 512
#define NBATCH 4096
#define LANES 32               // batches per CTA (= lanes per warp)
#define UPT 5                  // units per thread
#define UG 10                  // warps per CTA
#define NTH (LANES*UG)         // 320 threads
#define NCTA (NBATCH/LANES)    // 128 CTAs
#define NP0 28                 // stored k-pairs for W0/W1i rows (25 h + x + bias + pad)
#define NP1 26                 // stored k-pairs for W1h rows (25 h + pad)

typedef unsigned long long u64;

__device__ __forceinline__ u64 pk2(float lo, float hi) {
    u64 r; asm("mov.b64 %0, {%1,%2};" : "=l"(r) : "f"(lo), "f"(hi)); return r;
}
__device__ __forceinline__ void upk2(u64 v, float& lo, float& hi) {
    asm("mov.b64 {%0,%1}, %2;" : "=f"(lo), "=f"(hi) : "l"(v));
}
// packed fp32x2 FMA (Blackwell 2x fp32 path; only reachable via PTX)
__device__ __forceinline__ u64 ffma2(u64 a, u64 b, u64 c) {
    u64 d; asm("fma.rn.f32x2 %0, %1, %2, %3;" : "=l"(d) : "l"(a), "l"(b), "l"(c)); return d;
}

__device__ __forceinline__ float sigf(float z) {
    return __fdividef(1.0f, 1.0f + __expf(-z));
}
__device__ __forceinline__ float tanhfast(float z) {
    return fmaf(2.0f, sigf(2.0f * z), -1.0f);
}

// smem layout (float offsets):
//  W0  [50u][4g][28 pairs]x2   11200   (u64 rows; pair25=(w_ih0,0), pair26=(bias0,0), pair27=0)
//  W1i [50u][4g][28 pairs]x2   11200   (pair25=0, pair26=(bias1,0), pair27=0)
//  W1h [50u][4g][26 pairs]x2   10400   (pair25=0)
//  hs0 [25p][32lane][2]         1600   (h pairs, interleaved for LDS.64 reload)
//  hs1 [25p][32lane][2]         1600
//  xs  [32]                       32
#define SM_W0   0
#define SM_W1I  11200
#define SM_W1H  22400
#define SM_HS0  32800
#define SM_HS1  34400
#define SM_XS   36000
#define SM_TOT  36032

__global__ void __launch_bounds__(NTH, 1)
lstm_kernel(const float* __restrict__ x,
            const float* __restrict__ w_ih0, const float* __restrict__ w_hh0,
            const float* __restrict__ b_ih0, const float* __restrict__ b_hh0,
            const float* __restrict__ w_ih1, const float* __restrict__ w_hh1,
            const float* __restrict__ b_ih1, const float* __restrict__ b_hh1,
            const float* __restrict__ fc_w,  const float* __restrict__ fc_b,
            float* __restrict__ out) {
    extern __shared__ float smem[];
    float* hs0 = smem + SM_HS0;
    float* hs1 = smem + SM_HS1;
    float* xs  = smem + SM_XS;

    const int tid  = threadIdx.x;
    const int lane = tid & 31;        // batch within CTA
    const int grp  = tid >> 5;        // unit group
    const int u0   = grp * UPT;
    const int b0   = blockIdx.x * LANES;

    // ---- stage W0 / W1i rows: [u][g][pair] (pairs over k, plus x/bias pairs) ----
    for (int i = tid; i < HDIM * 4 * NP0; i += NTH) {
        int u = i / (4 * NP0);
        int r = i % (4 * NP0);
        int g = r / NP0;
        int p = r % NP0;
        int gi = g * HDIM + u;        // row index in [4H, *] matrices
        float a0 = 0.f, a1 = 0.f, e0 = 0.f, e1 = 0.f;
        if (p < 25) {
            a0 = w_hh0[gi * HDIM + 2 * p]; a1 = w_hh0[gi * HDIM + 2 * p + 1];
            e0 = w_ih1[gi * HDIM + 2 * p]; e1 = w_ih1[gi * HDIM + 2 * p + 1];
        } else if (p == 25) {
            a0 = w_ih0[gi];               // layer0 input weight (input dim 1)
        } else if (p == 26) {
            a0 = b_ih0[gi] + b_hh0[gi];   // combined layer0 bias
            e0 = b_ih1[gi] + b_hh1[gi];   // combined layer1 bias
        }
        smem[SM_W0  + 2 * i] = a0;  smem[SM_W0  + 2 * i + 1] = a1;
        smem[SM_W1I + 2 * i] = e0;  smem[SM_W1I + 2 * i + 1] = e1;
    }
    // ---- stage W1h rows (26 pairs) ----
    for (int i = tid; i < HDIM * 4 * NP1; i += NTH) {
        int u = i / (4 * NP1);
        int r = i % (4 * NP1);
        int g = r / NP1;
        int p = r % NP1;
        int gi = g * HDIM + u;
        float v0 = 0.f, v1 = 0.f;
        if (p < 25) {
            v0 = w_hh1[gi * HDIM + 2 * p]; v1 = w_hh1[gi * HDIM + 2 * p + 1];
        }
        smem[SM_W1H + 2 * i] = v0;  smem[SM_W1H + 2 * i + 1] = v1;
    }
    if (tid < LANES) xs[tid] = x[(size_t)(b0 + tid) * TLEN];
    __syncthreads();

    const u64* W0p  = (const u64*)(smem + SM_W0);
    const u64* W1ip = (const u64*)(smem + SM_W1I);
    const u64* W1hp = (const u64*)(smem + SM_W1H);

    // register-resident h pairs for this lane's batch
    u64 h0p[NP0];   // pairs 0..24 = h0, 25 = (x,0), 26 = (1,0), 27 = 0
    u64 h1p[NP1];   // pairs 0..24 = h1, 25 = 0
#pragma unroll
    for (int p = 0; p < NP0; p++) h0p[p] = 0ull;
#pragma unroll
    for (int p = 0; p < NP1; p++) h1p[p] = 0ull;
    h0p[26] = pk2(1.0f, 0.0f);

    float c0[UPT], c1[UPT], hn1[UPT];
#pragma unroll
    for (int j = 0; j < UPT; j++) { c0[j] = 0.0f; c1[j] = 0.0f; hn1[j] = 0.0f; }

#pragma unroll 1
    for (int t = 0; t < TLEN; t++) {
        // ===== Phase A: layer 0, all terms as k-pairs (incl. x and bias) =====
        h0p[25] = pk2(xs[lane], 0.0f);
        u64 acc[UPT][4];
#pragma unroll
        for (int j = 0; j < UPT; j++)
#pragma unroll
            for (int g = 0; g < 4; g++) acc[j][g] = 0ull;

#pragma unroll
        for (int q = 0; q < NP0 / 2; q++) {
            u64 ha = h0p[2 * q], hb = h0p[2 * q + 1];
#pragma unroll
            for (int j = 0; j < UPT; j++)
#pragma unroll
                for (int g = 0; g < 4; g++) {
                    ulonglong2 w2 = *(const ulonglong2*)(W0p + ((u0 + j) * 4 + g) * NP0 + 2 * q);
                    acc[j][g] = ffma2(w2.x, ha, acc[j][g]);
                    acc[j][g] = ffma2(w2.y, hb, acc[j][g]);
                }
        }
#pragma unroll
        for (int j = 0; j < UPT; j++) {
            float l, h, zi, zf, zg, zo;
            upk2(acc[j][0], l, h); zi = l + h;
            upk2(acc[j][1], l, h); zf = l + h;
            upk2(acc[j][2], l, h); zg = l + h;
            upk2(acc[j][3], l, h); zo = l + h;
            float ig = sigf(zi), fg = sigf(zf), gg = tanhfast(zg), og = sigf(zo);
            c0[j] = fmaf(fg, c0[j], ig * gg);
            float hn = og * tanhfast(c0[j]);
            int u = u0 + j;
            hs0[(u >> 1) * 64 + lane * 2 + (u & 1)] = hn;
        }
        __syncthreads();
        // reload h0(t) pairs
#pragma unroll
        for (int p = 0; p < 25; p++)
            h0p[p] = *(const u64*)(hs0 + p * 64 + lane * 2);

        // ===== Phase B: layer 1 = W1i @ h0(t) (+bias pair) + W1h @ h1(t-1) =====
#pragma unroll
        for (int j = 0; j < UPT; j++)
#pragma unroll
            for (int g = 0; g < 4; g++) acc[j][g] = 0ull;

#pragma unroll
        for (int q = 0; q < NP0 / 2; q++) {
            u64 ha = h0p[2 * q], hb = h0p[2 * q + 1];
#pragma unroll
            for (int j = 0; j < UPT; j++)
#pragma unroll
                for (int g = 0; g < 4; g++) {
                    ulonglong2 w2 = *(const ulonglong2*)(W1ip + ((u0 + j) * 4 + g) * NP0 + 2 * q);
                    acc[j][g] = ffma2(w2.x, ha, acc[j][g]);
                    acc[j][g] = ffma2(w2.y, hb, acc[j][g]);
                }
        }
#pragma unroll
        for (int q = 0; q < NP1 / 2; q++) {
            u64 ha = h1p[2 * q], hb = h1p[2 * q + 1];
#pragma unroll
            for (int j = 0; j < UPT; j++)
#pragma unroll
                for (int g = 0; g < 4; g++) {
                    ulonglong2 w2 = *(const ulonglong2*)(W1hp + ((u0 + j) * 4 + g) * NP1 + 2 * q);
                    acc[j][g] = ffma2(w2.x, ha, acc[j][g]);
                    acc[j][g] = ffma2(w2.y, hb, acc[j][g]);
                }
        }
#pragma unroll
        for (int j = 0; j < UPT; j++) {
            float l, h, zi, zf, zg, zo;
            upk2(acc[j][0], l, h); zi = l + h;
            upk2(acc[j][1], l, h); zf = l + h;
            upk2(acc[j][2], l, h); zg = l + h;
            upk2(acc[j][3], l, h); zo = l + h;
            float ig = sigf(zi), fg = sigf(zf), gg = tanhfast(zg), og = sigf(zo);
            c1[j] = fmaf(fg, c1[j], ig * gg);
            hn1[j] = og * tanhfast(c1[j]);
            int u = u0 + j;
            hs1[(u >> 1) * 64 + lane * 2 + (u & 1)] = hn1[j];
        }
        // stage x(t+1)
        if (tid < LANES && (t + 1) < TLEN)
            xs[tid] = x[(size_t)(b0 + tid) * TLEN + (t + 1)];
        __syncthreads();
        // reload h1(t) pairs
#pragma unroll
        for (int p = 0; p < 25; p++)
            h1p[p] = *(const u64*)(hs1 + p * 64 + lane * 2);
    }

    // ===== FC epilogue: out[b] = fc_w . h1(T-1)[b] + fc_b =====
    {
        float p = 0.0f;
#pragma unroll
        for (int j = 0; j < UPT; j++) p += fc_w[u0 + j] * hn1[j];
        float* red = hs0;                 // reuse as [grp][lane] scratch
        red[grp * LANES + lane] = p;
        __syncthreads();
        if (tid < LANES) {
            float s = fc_b[0];
#pragma unroll
            for (int g = 0; g < UG; g++) s += red[g * LANES + tid];
            out[b0 + tid] = s;
        }
    }
}

extern "C" void kernel_launch(void* const* d_in, const int* in_sizes, int n_in,
                              void* d_out, int out_size) {
    const float* x     = (const float*)d_in[0];
    const float* w_ih0 = (const float*)d_in[1];
    const float* w_hh0 = (const float*)d_in[2];
    const float* b_ih0 = (const float*)d_in[3];
    const float* b_hh0 = (const float*)d_in[4];
    const float* w_ih1 = (const float*)d_in[5];
    const float* w_hh1 = (const float*)d_in[6];
    const float* b_ih1 = (const float*)d_in[7];
    const float* b_hh1 = (const float*)d_in[8];
    const float* fc_w  = (const float*)d_in[9];
    const float* fc_b  = (const float*)d_in[10];
    float* out = (float*)d_out;

    const size_t smem_bytes = SM_TOT * sizeof(float);
    cudaFuncSetAttribute(lstm_kernel, cudaFuncAttributeMaxDynamicSharedMemorySize,
                         (int)smem_bytes);
    lstm_kernel<<<NCTA, NTH, smem_bytes>>>(x, w_ih0, w_hh0, b_ih0, b_hh0,
                                           w_ih1, w_hh1, b_ih1, b_hh1,
                                           fc_w, fc_b, out);
}

// round 10
// speedup vs baseline: 2.6044x; 2.6044x over previous
#include <cuda_runtime.h>
#include <cuda_bf16.h>
#include <cstdint>

#define HDIM 50
#define TLEN 512
#define NB 32
#define NWARP 13
#define NTH (NWARP*32)          // 416
#define NCTA 128
#define KT0 4                   // phase A k-tiles (K=64, real 52)
#define KT1 7                   // phase B k-tiles (K=112, real 101)
#define GP 36                   // G pitch (floats)
#define BPQ 34                  // B pitch (uint4 words per row) -> conflict-free

// ---- smem offsets (bytes) ----
#define OFF_WA0 0
#define SZ_WA0  (NWARP*KT0*2*32*16)      // 53248
#define OFF_WA1 (OFF_WA0+SZ_WA0)
#define SZ_WA1  (NWARP*KT1*2*32*16)      // 93184
#define OFF_BQ0 (OFF_WA1+SZ_WA1)         // 146432
#define SZ_BQ0  (KT0*4*BPQ*16)           // 8704
#define OFF_BQ1 (OFF_BQ0+SZ_BQ0)
#define SZ_BQ1  (KT1*4*BPQ*16)           // 15232
#define OFF_G   (OFF_BQ1+SZ_BQ1)         // 170368
#define SZ_G    (NWARP*16*GP*4)          // 29952
#define OFF_XB  (OFF_G+SZ_G)
#define SZ_XB   (32*32*4)                // 4096
#define SMEM_BYTES (OFF_XB+SZ_XB)        // 204416

__device__ __forceinline__ float sigf(float z) {
    return __fdividef(1.0f, 1.0f + __expf(-z));
}
__device__ __forceinline__ float tanhfast(float z) {
    return fmaf(2.0f, sigf(2.0f * z), -1.0f);
}
__device__ __forceinline__ unsigned short us16(float f) {
    return __bfloat16_as_ushort(__float2bfloat16(f));
}
__device__ __forceinline__ uint32_t pkbf(float e, float o) {   // low16=e (even k), high16=o (odd k)
    return (uint32_t)us16(e) | ((uint32_t)us16(o) << 16);
}
__device__ __forceinline__ float bfhi(float f) {
    return __bfloat162float(__float2bfloat16(f));
}
// u16 index of element (k, n) term0 in a Bq buffer; term1 at +2
__device__ __forceinline__ int bidx16(int k, int n) {
    int k2 = k >> 1, kt = k2 >> 3, rr = k2 & 7;
    return ((kt * 4 + (rr & 3)) * BPQ + n) * 8 + (rr >> 2) * 4 + (k & 1);
}
__device__ __forceinline__ void mma_bf16(float d[4], uint32_t a0, uint32_t a1,
                                         uint32_t a2, uint32_t a3,
                                         uint32_t b0, uint32_t b1) {
    asm volatile(
        "mma.sync.aligned.m16n8k16.row.col.f32.bf16.bf16.f32 "
        "{%0,%1,%2,%3}, {%4,%5,%6,%7}, {%8,%9}, {%0,%1,%2,%3};"
        : "+f"(d[0]), "+f"(d[1]), "+f"(d[2]), "+f"(d[3])
        : "r"(a0), "r"(a1), "r"(a2), "r"(a3), "r"(b0), "r"(b1));
}

__global__ void __launch_bounds__(NTH, 1)
lstm_kernel(const float* __restrict__ x,
            const float* __restrict__ w_ih0, const float* __restrict__ w_hh0,
            const float* __restrict__ b_ih0, const float* __restrict__ b_hh0,
            const float* __restrict__ w_ih1, const float* __restrict__ w_hh1,
            const float* __restrict__ b_ih1, const float* __restrict__ b_hh1,
            const float* __restrict__ fc_w,  const float* __restrict__ fc_b,
            float* __restrict__ out) {
    extern __shared__ char sm[];
    uint4* WA0 = (uint4*)(sm + OFF_WA0);
    uint4* WA1 = (uint4*)(sm + OFF_WA1);
    uint4* Bq0 = (uint4*)(sm + OFF_BQ0);
    uint4* Bq1 = (uint4*)(sm + OFF_BQ1);
    unsigned short* B0h = (unsigned short*)(sm + OFF_BQ0);
    unsigned short* B1h = (unsigned short*)(sm + OFF_BQ1);
    float* Gf = (float*)(sm + OFF_G);
    float* xb = (float*)(sm + OFF_XB);

    const int tid = threadIdx.x, lane = tid & 31, w = tid >> 5;
    const int g4 = lane >> 2, t4 = lane & 3;
    const int b0g = blockIdx.x * NB;

    // weight element getter (row R of [208,K] A matrix, col k)
    auto wld = [&](int ph, int R, int k) -> float {
        if (R >= 4 * HDIM) return 0.f;
        int u = R >> 2, gate = R & 3, gi = gate * HDIM + u;
        if (ph == 0) {
            if (k < HDIM)      return w_hh0[gi * HDIM + k];
            if (k == HDIM)     return w_ih0[gi];
            if (k == HDIM + 1) return b_ih0[gi] + b_hh0[gi];
            return 0.f;
        } else {
            if (k < HDIM)      return w_ih1[gi * HDIM + k];
            if (k < 2 * HDIM)  return w_hh1[gi * HDIM + k - HDIM];
            if (k == 2 * HDIM) return b_ih1[gi] + b_hh1[gi];
            return 0.f;
        }
    };
    auto wspl = [&](int ph, int R, int k, int term) -> float {
        float f = wld(ph, R, k);
        float fh = bfhi(f);
        return term ? (f - fh) : fh;
    };

    // ---- build A fragments (hi/lo), frag-order packed ----
    for (int i = tid; i < NWARP * (KT0 + KT1) * 2 * 32; i += NTH) {
        int ln = i & 31;
        int rest = i >> 5;
        int term = rest & 1;
        int tile = rest >> 1;
        int ph, mt, kt;
        if (tile < NWARP * KT0) { ph = 0; mt = tile / KT0; kt = tile % KT0; }
        else { int tt = tile - NWARP * KT0; ph = 1; mt = tt / KT1; kt = tt % KT1; }
        int gg = ln >> 2, tt4 = ln & 3;
        int R0 = mt * 16 + gg, R1 = R0 + 8, k0 = kt * 16;
        uint4 v;
        v.x = pkbf(wspl(ph, R0, k0 + 2 * tt4,     term), wspl(ph, R0, k0 + 2 * tt4 + 1, term));
        v.y = pkbf(wspl(ph, R1, k0 + 2 * tt4,     term), wspl(ph, R1, k0 + 2 * tt4 + 1, term));
        v.z = pkbf(wspl(ph, R0, k0 + 2 * tt4 + 8, term), wspl(ph, R0, k0 + 2 * tt4 + 9, term));
        v.w = pkbf(wspl(ph, R1, k0 + 2 * tt4 + 8, term), wspl(ph, R1, k0 + 2 * tt4 + 9, term));
        if (ph == 0) WA0[((mt * KT0 + kt) * 2 + term) * 32 + ln] = v;
        else         WA1[((mt * KT1 + kt) * 2 + term) * 32 + ln] = v;
    }
    // zero B buffers (contiguous)
    for (int i = tid; i < (SZ_BQ0 + SZ_BQ1) / 4; i += NTH)
        ((uint32_t*)(sm + OFF_BQ0))[i] = 0u;
    // xbuf chunk [0,32)
    if (tid < 256) {
        int bb = tid & 31, tq = (tid >> 5) * 4;
        float4 v = *(const float4*)(x + (size_t)(b0g + bb) * TLEN + tq);
        xb[(tq + 0) * 32 + bb] = v.x; xb[(tq + 1) * 32 + bb] = v.y;
        xb[(tq + 2) * 32 + bb] = v.z; xb[(tq + 3) * 32 + bb] = v.w;
    }
    __syncthreads();
    // bias columns + x(0)
    if (tid < 32) {
        float f = x[(size_t)(b0g + tid) * TLEN];
        float fh = bfhi(f);
        B0h[bidx16(50, tid)]     = us16(fh);
        B0h[bidx16(50, tid) + 2] = us16(f - fh);
        B0h[bidx16(51, tid)]     = us16(1.0f);
        B1h[bidx16(100, tid)]    = us16(1.0f);
    }
    __syncthreads();

    const int ul = lane >> 3;            // unit-local 0..3
    const int b4 = (lane & 7) * 4;       // first of 4 batches
    const int uu = 4 * w + ul;
    const bool uok = (uu < HDIM);
    float* Gw = Gf + w * 16 * GP;

    float c0[4], c1[4], h1v[4];
#pragma unroll
    for (int j = 0; j < 4; j++) { c0[j] = 0.f; c1[j] = 0.f; h1v[j] = 0.f; }

#pragma unroll 1
    for (int t = 0; t < TLEN; t++) {
        // xbuf refill (chunk [t+1, t+33)); barrier-ordered vs all xb reads
        if (((t + 1) & 31) == 0 && (t + 1) < TLEN && tid < 256) {
            int bb = tid & 31, tq = (tid >> 5) * 4;
            float4 v = *(const float4*)(x + (size_t)(b0g + bb) * TLEN + (t + 1) + tq);
            xb[((tq + 0) & 31) * 32 + bb] = v.x; xb[((tq + 1) & 31) * 32 + bb] = v.y;
            xb[((tq + 2) & 31) * 32 + bb] = v.z; xb[((tq + 3) & 31) * 32 + bb] = v.w;
        }

        float d[4][4];
        // ===== Phase A: G0 = A0 @ B0^T =====
#pragma unroll
        for (int nt = 0; nt < 4; nt++)
#pragma unroll
            for (int i2 = 0; i2 < 4; i2++) d[nt][i2] = 0.f;
#pragma unroll
        for (int kt = 0; kt < KT0; kt++) {
            uint4 Ah = WA0[((w * KT0 + kt) * 2 + 0) * 32 + lane];
            uint4 Al = WA0[((w * KT0 + kt) * 2 + 1) * 32 + lane];
#pragma unroll
            for (int nt = 0; nt < 4; nt++) {
                uint4 bq = Bq0[(kt * 4 + t4) * BPQ + nt * 8 + g4];
                mma_bf16(d[nt], Ah.x, Ah.y, Ah.z, Ah.w, bq.x, bq.z);   // hi*hi
                mma_bf16(d[nt], Ah.x, Ah.y, Ah.z, Ah.w, bq.y, bq.w);   // hi*lo
                mma_bf16(d[nt], Al.x, Al.y, Al.z, Al.w, bq.x, bq.z);   // lo*hi
            }
        }
        __syncthreads();                       // B0 reads complete before h0 writes
        // ---- epilogue A ----
#pragma unroll
        for (int nt = 0; nt < 4; nt++) {
            Gw[g4 * GP + nt * 8 + 2 * t4]           = d[nt][0];
            Gw[g4 * GP + nt * 8 + 2 * t4 + 1]       = d[nt][1];
            Gw[(g4 + 8) * GP + nt * 8 + 2 * t4]     = d[nt][2];
            Gw[(g4 + 8) * GP + nt * 8 + 2 * t4 + 1] = d[nt][3];
        }
        __syncwarp();
        {
            float4 gv0 = *(float4*)(Gw + (4 * ul + 0) * GP + b4);
            float4 gv1 = *(float4*)(Gw + (4 * ul + 1) * GP + b4);
            float4 gv2 = *(float4*)(Gw + (4 * ul + 2) * GP + b4);
            float4 gv3 = *(float4*)(Gw + (4 * ul + 3) * GP + b4);
            if (uok) {
                float* pi = (float*)&gv0; float* pf = (float*)&gv1;
                float* pg = (float*)&gv2; float* po = (float*)&gv3;
#pragma unroll
                for (int j = 0; j < 4; j++) {
                    float ig = sigf(pi[j]), fg = sigf(pf[j]);
                    float gg = tanhfast(pg[j]), og = sigf(po[j]);
                    c0[j] = fmaf(fg, c0[j], ig * gg);
                    float hn = og * tanhfast(c0[j]);
                    float hh = bfhi(hn);
                    unsigned short hb = us16(hn), lb = us16(hn - hh);
                    int i0 = bidx16(uu, b4 + j);
                    B0h[i0] = hb; B0h[i0 + 2] = lb;    // next-step recurrent
                    B1h[i0] = hb; B1h[i0 + 2] = lb;    // layer-1 input
                }
            }
        }
        __syncthreads();                       // h0 visible before phase B reads

        // ===== Phase B: G1 = A1 @ B1^T =====
#pragma unroll
        for (int nt = 0; nt < 4; nt++)
#pragma unroll
            for (int i2 = 0; i2 < 4; i2++) d[nt][i2] = 0.f;
#pragma unroll
        for (int kt = 0; kt < KT1; kt++) {
            uint4 Ah = WA1[((w * KT1 + kt) * 2 + 0) * 32 + lane];
            uint4 Al = WA1[((w * KT1 + kt) * 2 + 1) * 32 + lane];
#pragma unroll
            for (int nt = 0; nt < 4; nt++) {
                uint4 bq = Bq1[(kt * 4 + t4) * BPQ + nt * 8 + g4];
                mma_bf16(d[nt], Ah.x, Ah.y, Ah.z, Ah.w, bq.x, bq.z);
                mma_bf16(d[nt], Ah.x, Ah.y, Ah.z, Ah.w, bq.y, bq.w);
                mma_bf16(d[nt], Al.x, Al.y, Al.z, Al.w, bq.x, bq.z);
            }
        }
        __syncthreads();                       // B1 reads complete before h1 writes
        // ---- epilogue B ----
#pragma unroll
        for (int nt = 0; nt < 4; nt++) {
            Gw[g4 * GP + nt * 8 + 2 * t4]           = d[nt][0];
            Gw[g4 * GP + nt * 8 + 2 * t4 + 1]       = d[nt][1];
            Gw[(g4 + 8) * GP + nt * 8 + 2 * t4]     = d[nt][2];
            Gw[(g4 + 8) * GP + nt * 8 + 2 * t4 + 1] = d[nt][3];
        }
        __syncwarp();
        {
            float4 gv0 = *(float4*)(Gw + (4 * ul + 0) * GP + b4);
            float4 gv1 = *(float4*)(Gw + (4 * ul + 1) * GP + b4);
            float4 gv2 = *(float4*)(Gw + (4 * ul + 2) * GP + b4);
            float4 gv3 = *(float4*)(Gw + (4 * ul + 3) * GP + b4);
            if (uok) {
                float* pi = (float*)&gv0; float* pf = (float*)&gv1;
                float* pg = (float*)&gv2; float* po = (float*)&gv3;
#pragma unroll
                for (int j = 0; j < 4; j++) {
                    float ig = sigf(pi[j]), fg = sigf(pf[j]);
                    float gg = tanhfast(pg[j]), og = sigf(po[j]);
                    c1[j] = fmaf(fg, c1[j], ig * gg);
                    float hn = og * tanhfast(c1[j]);
                    h1v[j] = hn;
                    float hh = bfhi(hn);
                    unsigned short hb = us16(hn), lb = us16(hn - hh);
                    int i1 = bidx16(50 + uu, b4 + j);
                    B1h[i1] = hb; B1h[i1 + 2] = lb;    // next-step recurrent
                }
            }
        }
        // x(t+1) -> B0 col k=50
        if (tid < 32 && (t + 1) < TLEN) {
            float f = xb[((t + 1) & 31) * 32 + tid];
            float fh = bfhi(f);
            B0h[bidx16(50, tid)]     = us16(fh);
            B0h[bidx16(50, tid) + 2] = us16(f - fh);
        }
        __syncthreads();                       // step boundary
    }

    // ===== FC epilogue: out[b] = fc_w . h1(T-1)[b] + fc_b =====
    __syncthreads();
    if (uok) {
        float fw = fc_w[uu];
#pragma unroll
        for (int j = 0; j < 4; j++) Gf[uu * 32 + b4 + j] = fw * h1v[j];
    }
    __syncthreads();
    if (tid < 32) {
        float s = fc_b[0];
#pragma unroll 10
        for (int k = 0; k < HDIM; k++) s += Gf[k * 32 + tid];
        out[b0g + tid] = s;
    }
}

extern "C" void kernel_launch(void* const* d_in, const int* in_sizes, int n_in,
                              void* d_out, int out_size) {
    const float* x     = (const float*)d_in[0];
    const float* w_ih0 = (const float*)d_in[1];
    const float* w_hh0 = (const float*)d_in[2];
    const float* b_ih0 = (const float*)d_in[3];
    const float* b_hh0 = (const float*)d_in[4];
    const float* w_ih1 = (const float*)d_in[5];
    const float* w_hh1 = (const float*)d_in[6];
    const float* b_ih1 = (const float*)d_in[7];
    const float* b_hh1 = (const float*)d_in[8];
    const float* fc_w  = (const float*)d_in[9];
    const float* fc_b  = (const float*)d_in[10];
    float* out = (float*)d_out;

    cudaFuncSetAttribute(lstm_kernel, cudaFuncAttributeMaxDynamicSharedMemorySize,
                         SMEM_BYTES);
    lstm_kernel<<<NCTA, NTH, SMEM_BYTES>>>(x, w_ih0, w_hh0, b_ih0, b_hh0,
                                           w_ih1, w_hh1, b_ih1, b_hh1,
                                           fc_w, fc_b, out);
}

// round 11
// speedup vs baseline: 2.9832x; 1.1455x over previous
#include <cuda_runtime.h>
#include <cuda_bf16.h>
#include <cstdint>

#define HDIM 50
#define TLEN 512
#define NB 32
#define NWARP 13
#define NTH (NWARP*32)          // 416
#define NCTA 128
#define KT0 4                   // phase A k-tiles (K=64, real 52)
#define KT1 7                   // phase B k-tiles (K=112, real 101)
#define GP 36                   // G pitch (floats)
#define BPQ 34                  // B pitch (uint4 words per row)

// ---- smem offsets (bytes) ----
#define OFF_WA0 0
#define SZ_WA0  (NWARP*KT0*2*32*16)      // 53248
#define OFF_WA1 (OFF_WA0+SZ_WA0)
#define SZ_WA1  (NWARP*KT1*2*32*16)      // 93184
#define OFF_BQ0 (OFF_WA1+SZ_WA1)         // 146432, double-buffered
#define SZ_BQ0  (KT0*4*BPQ*16)           // 8704
#define OFF_BQ1 (OFF_BQ0+2*SZ_BQ0)       // 163840, double-buffered
#define SZ_BQ1  (KT1*4*BPQ*16)           // 15232
#define OFF_G   (OFF_BQ1+2*SZ_BQ1)       // 194304
#define SZ_G    (NWARP*16*GP*4)          // 29952
#define SMEM_BYTES (OFF_G+SZ_G)          // 224256

#define B0W (SZ_BQ0/16)         // uint4 per B0 buffer
#define B1W (SZ_BQ1/16)
#define B0H (SZ_BQ0/2)          // u16 per B0 buffer
#define B1H (SZ_BQ1/2)

__device__ __forceinline__ float sigf(float z) {
    return __fdividef(1.0f, 1.0f + __expf(-z));
}
__device__ __forceinline__ float tanhfast(float z) {
    return fmaf(2.0f, sigf(2.0f * z), -1.0f);
}
__device__ __forceinline__ unsigned short us16(float f) {
    return __bfloat16_as_ushort(__float2bfloat16(f));
}
__device__ __forceinline__ uint32_t pkbf(float e, float o) {
    return (uint32_t)us16(e) | ((uint32_t)us16(o) << 16);
}
__device__ __forceinline__ float bfhi(float f) {
    return __bfloat162float(__float2bfloat16(f));
}
// u16 index of element (k, n) term0 within one B buffer; term1 at +2
__device__ __forceinline__ int bidx16(int k, int n) {
    int k2 = k >> 1, kt = k2 >> 3, rr = k2 & 7;
    return ((kt * 4 + (rr & 3)) * BPQ + n) * 8 + (rr >> 2) * 4 + (k & 1);
}
__device__ __forceinline__ void mma_bf16(float d[4], uint32_t a0, uint32_t a1,
                                         uint32_t a2, uint32_t a3,
                                         uint32_t b0, uint32_t b1) {
    asm volatile(
        "mma.sync.aligned.m16n8k16.row.col.f32.bf16.bf16.f32 "
        "{%0,%1,%2,%3}, {%4,%5,%6,%7}, {%8,%9}, {%0,%1,%2,%3};"
        : "+f"(d[0]), "+f"(d[1]), "+f"(d[2]), "+f"(d[3])
        : "r"(a0), "r"(a1), "r"(a2), "r"(a3), "r"(b0), "r"(b1));
}

__global__ void __launch_bounds__(NTH, 1)
lstm_kernel(const float* __restrict__ x,
            const float* __restrict__ w_ih0, const float* __restrict__ w_hh0,
            const float* __restrict__ b_ih0, const float* __restrict__ b_hh0,
            const float* __restrict__ w_ih1, const float* __restrict__ w_hh1,
            const float* __restrict__ b_ih1, const float* __restrict__ b_hh1,
            const float* __restrict__ fc_w,  const float* __restrict__ fc_b,
            float* __restrict__ out) {
    extern __shared__ char sm[];
    uint4* WA0 = (uint4*)(sm + OFF_WA0);
    uint4* WA1 = (uint4*)(sm + OFF_WA1);
    uint4* Bq0 = (uint4*)(sm + OFF_BQ0);
    uint4* Bq1 = (uint4*)(sm + OFF_BQ1);
    unsigned short* B0h = (unsigned short*)(sm + OFF_BQ0);
    unsigned short* B1h = (unsigned short*)(sm + OFF_BQ1);
    float* Gf = (float*)(sm + OFF_G);

    const int tid = threadIdx.x, lane = tid & 31, w = tid >> 5;
    const int g4 = lane >> 2, t4 = lane & 3;
    const int b0g = blockIdx.x * NB;

    auto wld = [&](int ph, int R, int k) -> float {
        if (R >= 4 * HDIM) return 0.f;
        int u = R >> 2, gate = R & 3, gi = gate * HDIM + u;
        if (ph == 0) {
            if (k < HDIM)      return w_hh0[gi * HDIM + k];
            if (k == HDIM)     return w_ih0[gi];
            if (k == HDIM + 1) return b_ih0[gi] + b_hh0[gi];
            return 0.f;
        } else {
            if (k < HDIM)      return w_ih1[gi * HDIM + k];
            if (k < 2 * HDIM)  return w_hh1[gi * HDIM + k - HDIM];
            if (k == 2 * HDIM) return b_ih1[gi] + b_hh1[gi];
            return 0.f;
        }
    };
    auto wspl = [&](int ph, int R, int k, int term) -> float {
        float f = wld(ph, R, k);
        float fh = bfhi(f);
        return term ? (f - fh) : fh;
    };

    // ---- build A fragments (hi/lo), frag-order packed ----
    for (int i = tid; i < NWARP * (KT0 + KT1) * 2 * 32; i += NTH) {
        int ln = i & 31;
        int rest = i >> 5;
        int term = rest & 1;
        int tile = rest >> 1;
        int ph, mt, kt;
        if (tile < NWARP * KT0) { ph = 0; mt = tile / KT0; kt = tile % KT0; }
        else { int tt = tile - NWARP * KT0; ph = 1; mt = tt / KT1; kt = tt % KT1; }
        int gg = ln >> 2, tt4 = ln & 3;
        int R0 = mt * 16 + gg, R1 = R0 + 8, k0 = kt * 16;
        uint4 v;
        v.x = pkbf(wspl(ph, R0, k0 + 2 * tt4,     term), wspl(ph, R0, k0 + 2 * tt4 + 1, term));
        v.y = pkbf(wspl(ph, R1, k0 + 2 * tt4,     term), wspl(ph, R1, k0 + 2 * tt4 + 1, term));
        v.z = pkbf(wspl(ph, R0, k0 + 2 * tt4 + 8, term), wspl(ph, R0, k0 + 2 * tt4 + 9, term));
        v.w = pkbf(wspl(ph, R1, k0 + 2 * tt4 + 8, term), wspl(ph, R1, k0 + 2 * tt4 + 9, term));
        if (ph == 0) WA0[((mt * KT0 + kt) * 2 + term) * 32 + ln] = v;
        else         WA1[((mt * KT1 + kt) * 2 + term) * 32 + ln] = v;
    }
    // zero all four B buffers (contiguous)
    for (int i = tid; i < (2 * SZ_BQ0 + 2 * SZ_BQ1) / 4; i += NTH)
        ((uint32_t*)(sm + OFF_BQ0))[i] = 0u;
    __syncthreads();
    // bias columns (both buffers) + x(0) -> B0[1], x(1) -> B0[0]
    if (tid < 32) {
        B0h[0 * B0H + bidx16(51, tid)]  = us16(1.0f);
        B0h[1 * B0H + bidx16(51, tid)]  = us16(1.0f);
        B1h[0 * B1H + bidx16(100, tid)] = us16(1.0f);
        B1h[1 * B1H + bidx16(100, tid)] = us16(1.0f);
        float f0 = x[(size_t)(b0g + tid) * TLEN + 0];
        float h0 = bfhi(f0);
        B0h[1 * B0H + bidx16(50, tid)]     = us16(h0);
        B0h[1 * B0H + bidx16(50, tid) + 2] = us16(f0 - h0);
        float f1 = x[(size_t)(b0g + tid) * TLEN + 1];
        float h1 = bfhi(f1);
        B0h[0 * B0H + bidx16(50, tid)]     = us16(h1);
        B0h[0 * B0H + bidx16(50, tid) + 2] = us16(f1 - h1);
    }
    __syncthreads();

    const int ul = lane >> 3;            // unit-local 0..3
    const int b4 = (lane & 7) * 4;       // first of 4 batches
    const int uu = 4 * w + ul;
    const bool uok = (uu < HDIM);
    float* Gw = Gf + w * 16 * GP;

    float c0[4], c1[4], h1v[4];
#pragma unroll
    for (int j = 0; j < 4; j++) { c0[j] = 0.f; c1[j] = 0.f; h1v[j] = 0.f; }

    // ===== Prologue: phase A only, reads B0[1] (h0=0, x(0), bias) -> h0(0) into buf 0 =====
    {
        float d0[4][4];
#pragma unroll
        for (int nt = 0; nt < 4; nt++)
#pragma unroll
            for (int i2 = 0; i2 < 4; i2++) d0[nt][i2] = 0.f;
#pragma unroll
        for (int kt = 0; kt < KT0; kt++) {
            uint4 Ah = WA0[((w * KT0 + kt) * 2 + 0) * 32 + lane];
            uint4 Al = WA0[((w * KT0 + kt) * 2 + 1) * 32 + lane];
#pragma unroll
            for (int nt = 0; nt < 4; nt++) {
                uint4 bq = Bq0[1 * B0W + (kt * 4 + t4) * BPQ + nt * 8 + g4];
                mma_bf16(d0[nt], Ah.x, Ah.y, Ah.z, Ah.w, bq.x, bq.z);
                mma_bf16(d0[nt], Ah.x, Ah.y, Ah.z, Ah.w, bq.y, bq.w);
                mma_bf16(d0[nt], Al.x, Al.y, Al.z, Al.w, bq.x, bq.z);
            }
        }
#pragma unroll
        for (int nt = 0; nt < 4; nt++) {
            Gw[g4 * GP + nt * 8 + 2 * t4]           = d0[nt][0];
            Gw[g4 * GP + nt * 8 + 2 * t4 + 1]       = d0[nt][1];
            Gw[(g4 + 8) * GP + nt * 8 + 2 * t4]     = d0[nt][2];
            Gw[(g4 + 8) * GP + nt * 8 + 2 * t4 + 1] = d0[nt][3];
        }
        __syncwarp();
        float4 gv0 = *(float4*)(Gw + (4 * ul + 0) * GP + b4);
        float4 gv1 = *(float4*)(Gw + (4 * ul + 1) * GP + b4);
        float4 gv2 = *(float4*)(Gw + (4 * ul + 2) * GP + b4);
        float4 gv3 = *(float4*)(Gw + (4 * ul + 3) * GP + b4);
        __syncwarp();
        if (uok) {
            float* pi = (float*)&gv0; float* pf = (float*)&gv1;
            float* pg = (float*)&gv2; float* po = (float*)&gv3;
#pragma unroll
            for (int j = 0; j < 4; j++) {
                float ig = sigf(pi[j]), fg = sigf(pf[j]);
                float gg = tanhfast(pg[j]), og = sigf(po[j]);
                c0[j] = fmaf(fg, c0[j], ig * gg);
                float hn = og * tanhfast(c0[j]);
                float hh = bfhi(hn);
                unsigned short hb = us16(hn), lb = us16(hn - hh);
                int i0 = bidx16(uu, b4 + j);
                B0h[0 * B0H + i0] = hb; B0h[0 * B0H + i0 + 2] = lb;
                B1h[0 * B1H + i0] = hb; B1h[0 * B1H + i0 + 2] = lb;
            }
        }
    }
    __syncthreads();

    // ===== Fused main loop: iteration i computes G0(i+1) and G1(i), ONE barrier =====
#pragma unroll 1
    for (int i = 0; i < TLEN - 1; i++) {
        const int cur = i & 1, nxt = cur ^ 1;

        // prefetch x(i+2) (latency hidden under MMA block)
        float xv = 0.f;
        if (w == 12 && (i + 2) < TLEN)
            xv = x[(size_t)(b0g + lane) * TLEN + (i + 2)];

        float d0[4][4], d1[4][4];
#pragma unroll
        for (int nt = 0; nt < 4; nt++)
#pragma unroll
            for (int i2 = 0; i2 < 4; i2++) { d0[nt][i2] = 0.f; d1[nt][i2] = 0.f; }

        // --- all 132 MMAs back-to-back: G0 from B0[cur], G1 from B1[cur] ---
#pragma unroll
        for (int kt = 0; kt < KT0; kt++) {
            uint4 Ah = WA0[((w * KT0 + kt) * 2 + 0) * 32 + lane];
            uint4 Al = WA0[((w * KT0 + kt) * 2 + 1) * 32 + lane];
#pragma unroll
            for (int nt = 0; nt < 4; nt++) {
                uint4 bq = Bq0[cur * B0W + (kt * 4 + t4) * BPQ + nt * 8 + g4];
                mma_bf16(d0[nt], Ah.x, Ah.y, Ah.z, Ah.w, bq.x, bq.z);
                mma_bf16(d0[nt], Ah.x, Ah.y, Ah.z, Ah.w, bq.y, bq.w);
                mma_bf16(d0[nt], Al.x, Al.y, Al.z, Al.w, bq.x, bq.z);
            }
        }
#pragma unroll
        for (int kt = 0; kt < KT1; kt++) {
            uint4 Ah = WA1[((w * KT1 + kt) * 2 + 0) * 32 + lane];
            uint4 Al = WA1[((w * KT1 + kt) * 2 + 1) * 32 + lane];
#pragma unroll
            for (int nt = 0; nt < 4; nt++) {
                uint4 bq = Bq1[cur * B1W + (kt * 4 + t4) * BPQ + nt * 8 + g4];
                mma_bf16(d1[nt], Ah.x, Ah.y, Ah.z, Ah.w, bq.x, bq.z);
                mma_bf16(d1[nt], Ah.x, Ah.y, Ah.z, Ah.w, bq.y, bq.w);
                mma_bf16(d1[nt], Al.x, Al.y, Al.z, Al.w, bq.x, bq.z);
            }
        }

        // --- epilogue 0: h0(i+1) -> B0[nxt], B1[nxt] ---
#pragma unroll
        for (int nt = 0; nt < 4; nt++) {
            Gw[g4 * GP + nt * 8 + 2 * t4]           = d0[nt][0];
            Gw[g4 * GP + nt * 8 + 2 * t4 + 1]       = d0[nt][1];
            Gw[(g4 + 8) * GP + nt * 8 + 2 * t4]     = d0[nt][2];
            Gw[(g4 + 8) * GP + nt * 8 + 2 * t4 + 1] = d0[nt][3];
        }
        __syncwarp();
        {
            float4 gv0 = *(float4*)(Gw + (4 * ul + 0) * GP + b4);
            float4 gv1 = *(float4*)(Gw + (4 * ul + 1) * GP + b4);
            float4 gv2 = *(float4*)(Gw + (4 * ul + 2) * GP + b4);
            float4 gv3 = *(float4*)(Gw + (4 * ul + 3) * GP + b4);
            __syncwarp();
            if (uok) {
                float* pi = (float*)&gv0; float* pf = (float*)&gv1;
                float* pg = (float*)&gv2; float* po = (float*)&gv3;
#pragma unroll
                for (int j = 0; j < 4; j++) {
                    float ig = sigf(pi[j]), fg = sigf(pf[j]);
                    float gg = tanhfast(pg[j]), og = sigf(po[j]);
                    c0[j] = fmaf(fg, c0[j], ig * gg);
                    float hn = og * tanhfast(c0[j]);
                    float hh = bfhi(hn);
                    unsigned short hb = us16(hn), lb = us16(hn - hh);
                    int i0 = bidx16(uu, b4 + j);
                    B0h[nxt * B0H + i0] = hb; B0h[nxt * B0H + i0 + 2] = lb;
                    B1h[nxt * B1H + i0] = hb; B1h[nxt * B1H + i0 + 2] = lb;
                }
            }
        }
        // --- epilogue 1: h1(i) -> B1[nxt] ---
#pragma unroll
        for (int nt = 0; nt < 4; nt++) {
            Gw[g4 * GP + nt * 8 + 2 * t4]           = d1[nt][0];
            Gw[g4 * GP + nt * 8 + 2 * t4 + 1]       = d1[nt][1];
            Gw[(g4 + 8) * GP + nt * 8 + 2 * t4]     = d1[nt][2];
            Gw[(g4 + 8) * GP + nt * 8 + 2 * t4 + 1] = d1[nt][3];
        }
        __syncwarp();
        {
            float4 gv0 = *(float4*)(Gw + (4 * ul + 0) * GP + b4);
            float4 gv1 = *(float4*)(Gw + (4 * ul + 1) * GP + b4);
            float4 gv2 = *(float4*)(Gw + (4 * ul + 2) * GP + b4);
            float4 gv3 = *(float4*)(Gw + (4 * ul + 3) * GP + b4);
            __syncwarp();
            if (uok) {
                float* pi = (float*)&gv0; float* pf = (float*)&gv1;
                float* pg = (float*)&gv2; float* po = (float*)&gv3;
#pragma unroll
                for (int j = 0; j < 4; j++) {
                    float ig = sigf(pi[j]), fg = sigf(pf[j]);
                    float gg = tanhfast(pg[j]), og = sigf(po[j]);
                    c1[j] = fmaf(fg, c1[j], ig * gg);
                    float hn = og * tanhfast(c1[j]);
                    h1v[j] = hn;
                    float hh = bfhi(hn);
                    unsigned short hb = us16(hn), lb = us16(hn - hh);
                    int i1 = bidx16(50 + uu, b4 + j);
                    B1h[nxt * B1H + i1] = hb; B1h[nxt * B1H + i1 + 2] = lb;
                }
            }
        }
        // x(i+2) -> B0[nxt] col 50
        if (w == 12 && (i + 2) < TLEN) {
            float fh = bfhi(xv);
            B0h[nxt * B0H + bidx16(50, lane)]     = us16(fh);
            B0h[nxt * B0H + bidx16(50, lane) + 2] = us16(xv - fh);
        }
        __syncthreads();
    }

    // ===== Tail: G1(511) from B1[1] -> h1(511) =====
    {
        const int cur = (TLEN - 1) & 1;   // 1
        float d1[4][4];
#pragma unroll
        for (int nt = 0; nt < 4; nt++)
#pragma unroll
            for (int i2 = 0; i2 < 4; i2++) d1[nt][i2] = 0.f;
#pragma unroll
        for (int kt = 0; kt < KT1; kt++) {
            uint4 Ah = WA1[((w * KT1 + kt) * 2 + 0) * 32 + lane];
            uint4 Al = WA1[((w * KT1 + kt) * 2 + 1) * 32 + lane];
#pragma unroll
            for (int nt = 0; nt < 4; nt++) {
                uint4 bq = Bq1[cur * B1W + (kt * 4 + t4) * BPQ + nt * 8 + g4];
                mma_bf16(d1[nt], Ah.x, Ah.y, Ah.z, Ah.w, bq.x, bq.z);
                mma_bf16(d1[nt], Ah.x, Ah.y, Ah.z, Ah.w, bq.y, bq.w);
                mma_bf16(d1[nt], Al.x, Al.y, Al.z, Al.w, bq.x, bq.z);
            }
        }
#pragma unroll
        for (int nt = 0; nt < 4; nt++) {
            Gw[g4 * GP + nt * 8 + 2 * t4]           = d1[nt][0];
            Gw[g4 * GP + nt * 8 + 2 * t4 + 1]       = d1[nt][1];
            Gw[(g4 + 8) * GP + nt * 8 + 2 * t4]     = d1[nt][2];
            Gw[(g4 + 8) * GP + nt * 8 + 2 * t4 + 1] = d1[nt][3];
        }
        __syncwarp();
        float4 gv0 = *(float4*)(Gw + (4 * ul + 0) * GP + b4);
        float4 gv1 = *(float4*)(Gw + (4 * ul + 1) * GP + b4);
        float4 gv2 = *(float4*)(Gw + (4 * ul + 2) * GP + b4);
        float4 gv3 = *(float4*)(Gw + (4 * ul + 3) * GP + b4);
        __syncwarp();
        if (uok) {
            float* pi = (float*)&gv0; float* pf = (float*)&gv1;
            float* pg = (float*)&gv2; float* po = (float*)&gv3;
#pragma unroll
            for (int j = 0; j < 4; j++) {
                float ig = sigf(pi[j]), fg = sigf(pf[j]);
                float gg = tanhfast(pg[j]), og = sigf(po[j]);
                c1[j] = fmaf(fg, c1[j], ig * gg);
                h1v[j] = og * tanhfast(c1[j]);
            }
        }
    }
    __syncthreads();

    // ===== FC epilogue: out[b] = fc_w . h1(511)[b] + fc_b =====
    if (uok) {
        float fw = fc_w[uu];
#pragma unroll
        for (int j = 0; j < 4; j++) Gf[uu * 32 + b4 + j] = fw * h1v[j];
    }
    __syncthreads();
    if (tid < 32) {
        float s = fc_b[0];
#pragma unroll 10
        for (int k = 0; k < HDIM; k++) s += Gf[k * 32 + tid];
        out[b0g + tid] = s;
    }
}

extern "C" void kernel_launch(void* const* d_in, const int* in_sizes, int n_in,
                              void* d_out, int out_size) {
    const float* x     = (const float*)d_in[0];
    const float* w_ih0 = (const float*)d_in[1];
    const float* w_hh0 = (const float*)d_in[2];
    const float* b_ih0 = (const float*)d_in[3];
    const float* b_hh0 = (const float*)d_in[4];
    const float* w_ih1 = (const float*)d_in[5];
    const float* w_hh1 = (const float*)d_in[6];
    const float* b_ih1 = (const float*)d_in[7];
    const float* b_hh1 = (const float*)d_in[8];
    const float* fc_w  = (const float*)d_in[9];
    const float* fc_b  = (const float*)d_in[10];
    float* out = (float*)d_out;

    cudaFuncSetAttribute(lstm_kernel, cudaFuncAttributeMaxDynamicSharedMemorySize,
                         SMEM_BYTES);
    lstm_kernel<<<NCTA, NTH, SMEM_BYTES>>>(x, w_ih0, w_hh0, b_ih0, b_hh0,
                                           w_ih1, w_hh1, b_ih1, b_hh1,
                                           fc_w, fc_b, out);
}

// round 12
// speedup vs baseline: 3.2377x; 1.0853x over previous
#include <cuda_runtime.h>
#include <cuda_bf16.h>
#include <cstdint>

#define HDIM 50
#define TLEN 512
#define NB 32
#define NWARP 13
#define NTH (NWARP*32)          // 416
#define NCTA 128
#define KT0 4                   // phase A k-tiles (K=64, real 52)
#define KT1 7                   // phase B k-tiles (K=112, real 101)
#define GP 36                   // G pitch (floats)
#define BPQ 34                  // B pitch (uint4 words per row)

// ---- smem offsets (bytes) ----
#define OFF_WA0 0
#define SZ_WA0  (NWARP*KT0*2*32*16)      // 53248
#define OFF_WA1 (OFF_WA0+SZ_WA0)
#define SZ_WA1  (NWARP*KT1*2*32*16)      // 93184
#define OFF_BQ0 (OFF_WA1+SZ_WA1)         // 146432, double-buffered
#define SZ_BQ0  (KT0*4*BPQ*16)           // 8704
#define OFF_BQ1 (OFF_BQ0+2*SZ_BQ0)       // 163840, double-buffered
#define SZ_BQ1  (KT1*4*BPQ*16)           // 15232
#define OFF_G   (OFF_BQ1+2*SZ_BQ1)       // 194304
#define SZ_G    (NWARP*16*GP*4)          // 29952
#define SMEM_BYTES (OFF_G+SZ_G)          // 224256

#define B0W (SZ_BQ0/16)
#define B1W (SZ_BQ1/16)
#define B0H (SZ_BQ0/2)
#define B1H (SZ_BQ1/2)

__device__ __forceinline__ float tanha(float z) {
    float r; asm("tanh.approx.f32 %0, %1;" : "=f"(r) : "f"(z)); return r;
}
__device__ __forceinline__ float sigf(float z) {
    return fmaf(0.5f, tanha(0.5f * z), 0.5f);
}
__device__ __forceinline__ unsigned short us16(float f) {
    return __bfloat16_as_ushort(__float2bfloat16(f));
}
__device__ __forceinline__ uint32_t pkbf(float e, float o) {
    return (uint32_t)us16(e) | ((uint32_t)us16(o) << 16);
}
__device__ __forceinline__ float bfhi(float f) {
    return __bfloat162float(__float2bfloat16(f));
}
__device__ __forceinline__ int bidx16(int k, int n) {
    int k2 = k >> 1, kt = k2 >> 3, rr = k2 & 7;
    return ((kt * 4 + (rr & 3)) * BPQ + n) * 8 + (rr >> 2) * 4 + (k & 1);
}
__device__ __forceinline__ void mma_bf16(float d[4], uint32_t a0, uint32_t a1,
                                         uint32_t a2, uint32_t a3,
                                         uint32_t b0, uint32_t b1) {
    asm volatile(
        "mma.sync.aligned.m16n8k16.row.col.f32.bf16.bf16.f32 "
        "{%0,%1,%2,%3}, {%4,%5,%6,%7}, {%8,%9}, {%0,%1,%2,%3};"
        : "+f"(d[0]), "+f"(d[1]), "+f"(d[2]), "+f"(d[3])
        : "r"(a0), "r"(a1), "r"(a2), "r"(a3), "r"(b0), "r"(b1));
}

__global__ void __launch_bounds__(NTH, 1)
lstm_kernel(const float* __restrict__ x,
            const float* __restrict__ w_ih0, const float* __restrict__ w_hh0,
            const float* __restrict__ b_ih0, const float* __restrict__ b_hh0,
            const float* __restrict__ w_ih1, const float* __restrict__ w_hh1,
            const float* __restrict__ b_ih1, const float* __restrict__ b_hh1,
            const float* __restrict__ fc_w,  const float* __restrict__ fc_b,
            float* __restrict__ out) {
    extern __shared__ char sm[];
    uint4* WA0 = (uint4*)(sm + OFF_WA0);
    uint4* WA1 = (uint4*)(sm + OFF_WA1);
    uint4* Bq0 = (uint4*)(sm + OFF_BQ0);
    uint4* Bq1 = (uint4*)(sm + OFF_BQ1);
    unsigned short* B0h = (unsigned short*)(sm + OFF_BQ0);
    unsigned short* B1h = (unsigned short*)(sm + OFF_BQ1);
    float* Gf = (float*)(sm + OFF_G);

    const int tid = threadIdx.x, lane = tid & 31, w = tid >> 5;
    const int g4 = lane >> 2, t4 = lane & 3;
    const int b0g = blockIdx.x * NB;

    auto wld = [&](int ph, int R, int k) -> float {
        if (R >= 4 * HDIM) return 0.f;
        int u = R >> 2, gate = R & 3, gi = gate * HDIM + u;
        if (ph == 0) {
            if (k < HDIM)      return w_hh0[gi * HDIM + k];
            if (k == HDIM)     return w_ih0[gi];
            if (k == HDIM + 1) return b_ih0[gi] + b_hh0[gi];
            return 0.f;
        } else {
            if (k < HDIM)      return w_ih1[gi * HDIM + k];
            if (k < 2 * HDIM)  return w_hh1[gi * HDIM + k - HDIM];
            if (k == 2 * HDIM) return b_ih1[gi] + b_hh1[gi];
            return 0.f;
        }
    };
    auto wspl = [&](int ph, int R, int k, int term) -> float {
        float f = wld(ph, R, k);
        float fh = bfhi(f);
        return term ? (f - fh) : fh;
    };

    // ---- build A fragments (hi/lo), frag-order packed ----
    for (int i = tid; i < NWARP * (KT0 + KT1) * 2 * 32; i += NTH) {
        int ln = i & 31;
        int rest = i >> 5;
        int term = rest & 1;
        int tile = rest >> 1;
        int ph, mt, kt;
        if (tile < NWARP * KT0) { ph = 0; mt = tile / KT0; kt = tile % KT0; }
        else { int tt = tile - NWARP * KT0; ph = 1; mt = tt / KT1; kt = tt % KT1; }
        int gg = ln >> 2, tt4 = ln & 3;
        int R0 = mt * 16 + gg, R1 = R0 + 8, k0 = kt * 16;
        uint4 v;
        v.x = pkbf(wspl(ph, R0, k0 + 2 * tt4,     term), wspl(ph, R0, k0 + 2 * tt4 + 1, term));
        v.y = pkbf(wspl(ph, R1, k0 + 2 * tt4,     term), wspl(ph, R1, k0 + 2 * tt4 + 1, term));
        v.z = pkbf(wspl(ph, R0, k0 + 2 * tt4 + 8, term), wspl(ph, R0, k0 + 2 * tt4 + 9, term));
        v.w = pkbf(wspl(ph, R1, k0 + 2 * tt4 + 8, term), wspl(ph, R1, k0 + 2 * tt4 + 9, term));
        if (ph == 0) WA0[((mt * KT0 + kt) * 2 + term) * 32 + ln] = v;
        else         WA1[((mt * KT1 + kt) * 2 + term) * 32 + ln] = v;
    }
    // zero all four B buffers (contiguous)
    for (int i = tid; i < (2 * SZ_BQ0 + 2 * SZ_BQ1) / 4; i += NTH)
        ((uint32_t*)(sm + OFF_BQ0))[i] = 0u;
    __syncthreads();
    // bias columns (both buffers) + x(0) -> B0[1], x(1) -> B0[0]
    if (tid < 32) {
        B0h[0 * B0H + bidx16(51, tid)]  = us16(1.0f);
        B0h[1 * B0H + bidx16(51, tid)]  = us16(1.0f);
        B1h[0 * B1H + bidx16(100, tid)] = us16(1.0f);
        B1h[1 * B1H + bidx16(100, tid)] = us16(1.0f);
        float f0 = x[(size_t)(b0g + tid) * TLEN + 0];
        float h0 = bfhi(f0);
        B0h[1 * B0H + bidx16(50, tid)]     = us16(h0);
        B0h[1 * B0H + bidx16(50, tid) + 2] = us16(f0 - h0);
        float f1 = x[(size_t)(b0g + tid) * TLEN + 1];
        float h1 = bfhi(f1);
        B0h[0 * B0H + bidx16(50, tid)]     = us16(h1);
        B0h[0 * B0H + bidx16(50, tid) + 2] = us16(f1 - h1);
    }
    __syncthreads();

    const int ul = lane >> 3;
    const int b4 = (lane & 7) * 4;
    const int uu = 4 * w + ul;
    const bool uok = (uu < HDIM);
    float* Gw = Gf + w * 16 * GP;

    // register-cache the loop-invariant A hi-fragments
    uint4 A0r[KT0], A1r[KT1];
#pragma unroll
    for (int kt = 0; kt < KT0; kt++) A0r[kt] = WA0[((w * KT0 + kt) * 2 + 0) * 32 + lane];
#pragma unroll
    for (int kt = 0; kt < KT1; kt++) A1r[kt] = WA1[((w * KT1 + kt) * 2 + 0) * 32 + lane];

    float c0[4], c1[4], h1v[4];
#pragma unroll
    for (int j = 0; j < 4; j++) { c0[j] = 0.f; c1[j] = 0.f; h1v[j] = 0.f; }

    // ===== Prologue: phase A only, reads B0[1] -> h0(0) into buf 0 =====
    {
        float d0[4][4];
#pragma unroll
        for (int nt = 0; nt < 4; nt++)
#pragma unroll
            for (int i2 = 0; i2 < 4; i2++) d0[nt][i2] = 0.f;
#pragma unroll
        for (int kt = 0; kt < KT0; kt++) {
            uint4 Ah = A0r[kt];
            uint4 Al = WA0[((w * KT0 + kt) * 2 + 1) * 32 + lane];
#pragma unroll
            for (int nt = 0; nt < 4; nt++) {
                uint4 bq = Bq0[1 * B0W + (kt * 4 + t4) * BPQ + nt * 8 + g4];
                mma_bf16(d0[nt], Ah.x, Ah.y, Ah.z, Ah.w, bq.x, bq.z);
                mma_bf16(d0[nt], Ah.x, Ah.y, Ah.z, Ah.w, bq.y, bq.w);
                mma_bf16(d0[nt], Al.x, Al.y, Al.z, Al.w, bq.x, bq.z);
            }
        }
#pragma unroll
        for (int nt = 0; nt < 4; nt++) {
            Gw[g4 * GP + nt * 8 + 2 * t4]           = d0[nt][0];
            Gw[g4 * GP + nt * 8 + 2 * t4 + 1]       = d0[nt][1];
            Gw[(g4 + 8) * GP + nt * 8 + 2 * t4]     = d0[nt][2];
            Gw[(g4 + 8) * GP + nt * 8 + 2 * t4 + 1] = d0[nt][3];
        }
        __syncwarp();
        float4 gv0 = *(float4*)(Gw + (4 * ul + 0) * GP + b4);
        float4 gv1 = *(float4*)(Gw + (4 * ul + 1) * GP + b4);
        float4 gv2 = *(float4*)(Gw + (4 * ul + 2) * GP + b4);
        float4 gv3 = *(float4*)(Gw + (4 * ul + 3) * GP + b4);
        __syncwarp();
        if (uok) {
            float* pi = (float*)&gv0; float* pf = (float*)&gv1;
            float* pg = (float*)&gv2; float* po = (float*)&gv3;
#pragma unroll
            for (int j = 0; j < 4; j++) {
                float ig = sigf(pi[j]), fg = sigf(pf[j]);
                float gg = tanha(pg[j]), og = sigf(po[j]);
                c0[j] = fmaf(fg, c0[j], ig * gg);
                float hn = og * tanha(c0[j]);
                float hh = bfhi(hn);
                unsigned short hb = us16(hn), lb = us16(hn - hh);
                int i0 = bidx16(uu, b4 + j);
                B0h[0 * B0H + i0] = hb; B0h[0 * B0H + i0 + 2] = lb;
                B1h[0 * B1H + i0] = hb; B1h[0 * B1H + i0 + 2] = lb;
            }
        }
    }
    __syncthreads();

    // ===== Fused main loop: iteration i computes G0(i+1) and G1(i), ONE barrier =====
#pragma unroll 1
    for (int i = 0; i < TLEN - 1; i++) {
        const int cur = i & 1, nxt = cur ^ 1;

        float xv = 0.f;
        if (w == 12 && (i + 2) < TLEN)
            xv = x[(size_t)(b0g + lane) * TLEN + (i + 2)];

        float d0[4][4], d1[4][4];
#pragma unroll
        for (int nt = 0; nt < 4; nt++)
#pragma unroll
            for (int i2 = 0; i2 < 4; i2++) { d0[nt][i2] = 0.f; d1[nt][i2] = 0.f; }

#pragma unroll
        for (int kt = 0; kt < KT0; kt++) {
            uint4 Ah = A0r[kt];
            uint4 Al = WA0[((w * KT0 + kt) * 2 + 1) * 32 + lane];
#pragma unroll
            for (int nt = 0; nt < 4; nt++) {
                uint4 bq = Bq0[cur * B0W + (kt * 4 + t4) * BPQ + nt * 8 + g4];
                mma_bf16(d0[nt], Ah.x, Ah.y, Ah.z, Ah.w, bq.x, bq.z);
                mma_bf16(d0[nt], Ah.x, Ah.y, Ah.z, Ah.w, bq.y, bq.w);
                mma_bf16(d0[nt], Al.x, Al.y, Al.z, Al.w, bq.x, bq.z);
            }
        }
#pragma unroll
        for (int kt = 0; kt < KT1; kt++) {
            uint4 Ah = A1r[kt];
            uint4 Al = WA1[((w * KT1 + kt) * 2 + 1) * 32 + lane];
#pragma unroll
            for (int nt = 0; nt < 4; nt++) {
                uint4 bq = Bq1[cur * B1W + (kt * 4 + t4) * BPQ + nt * 8 + g4];
                mma_bf16(d1[nt], Ah.x, Ah.y, Ah.z, Ah.w, bq.x, bq.z);
                mma_bf16(d1[nt], Ah.x, Ah.y, Ah.z, Ah.w, bq.y, bq.w);
                mma_bf16(d1[nt], Al.x, Al.y, Al.z, Al.w, bq.x, bq.z);
            }
        }

        // --- epilogue 0: h0(i+1) -> B0[nxt], B1[nxt] ---
#pragma unroll
        for (int nt = 0; nt < 4; nt++) {
            Gw[g4 * GP + nt * 8 + 2 * t4]           = d0[nt][0];
            Gw[g4 * GP + nt * 8 + 2 * t4 + 1]       = d0[nt][1];
            Gw[(g4 + 8) * GP + nt * 8 + 2 * t4]     = d0[nt][2];
            Gw[(g4 + 8) * GP + nt * 8 + 2 * t4 + 1] = d0[nt][3];
        }
        __syncwarp();
        {
            float4 gv0 = *(float4*)(Gw + (4 * ul + 0) * GP + b4);
            float4 gv1 = *(float4*)(Gw + (4 * ul + 1) * GP + b4);
            float4 gv2 = *(float4*)(Gw + (4 * ul + 2) * GP + b4);
            float4 gv3 = *(float4*)(Gw + (4 * ul + 3) * GP + b4);
            __syncwarp();
            if (uok) {
                float* pi = (float*)&gv0; float* pf = (float*)&gv1;
                float* pg = (float*)&gv2; float* po = (float*)&gv3;
#pragma unroll
                for (int j = 0; j < 4; j++) {
                    float ig = sigf(pi[j]), fg = sigf(pf[j]);
                    float gg = tanha(pg[j]), og = sigf(po[j]);
                    c0[j] = fmaf(fg, c0[j], ig * gg);
                    float hn = og * tanha(c0[j]);
                    float hh = bfhi(hn);
                    unsigned short hb = us16(hn), lb = us16(hn - hh);
                    int i0 = bidx16(uu, b4 + j);
                    B0h[nxt * B0H + i0] = hb; B0h[nxt * B0H + i0 + 2] = lb;
                    B1h[nxt * B1H + i0] = hb; B1h[nxt * B1H + i0 + 2] = lb;
                }
            }
        }
        // --- epilogue 1: h1(i) -> B1[nxt] ---
#pragma unroll
        for (int nt = 0; nt < 4; nt++) {
            Gw[g4 * GP + nt * 8 + 2 * t4]           = d1[nt][0];
            Gw[g4 * GP + nt * 8 + 2 * t4 + 1]       = d1[nt][1];
            Gw[(g4 + 8) * GP + nt * 8 + 2 * t4]     = d1[nt][2];
            Gw[(g4 + 8) * GP + nt * 8 + 2 * t4 + 1] = d1[nt][3];
        }
        __syncwarp();
        {
            float4 gv0 = *(float4*)(Gw + (4 * ul + 0) * GP + b4);
            float4 gv1 = *(float4*)(Gw + (4 * ul + 1) * GP + b4);
            float4 gv2 = *(float4*)(Gw + (4 * ul + 2) * GP + b4);
            float4 gv3 = *(float4*)(Gw + (4 * ul + 3) * GP + b4);
            __syncwarp();
            if (uok) {
                float* pi = (float*)&gv0; float* pf = (float*)&gv1;
                float* pg = (float*)&gv2; float* po = (float*)&gv3;
#pragma unroll
                for (int j = 0; j < 4; j++) {
                    float ig = sigf(pi[j]), fg = sigf(pf[j]);
                    float gg = tanha(pg[j]), og = sigf(po[j]);
                    c1[j] = fmaf(fg, c1[j], ig * gg);
                    float hn = og * tanha(c1[j]);
                    h1v[j] = hn;
                    float hh = bfhi(hn);
                    unsigned short hb = us16(hn), lb = us16(hn - hh);
                    int i1 = bidx16(50 + uu, b4 + j);
                    B1h[nxt * B1H + i1] = hb; B1h[nxt * B1H + i1 + 2] = lb;
                }
            }
        }
        if (w == 12 && (i + 2) < TLEN) {
            float fh = bfhi(xv);
            B0h[nxt * B0H + bidx16(50, lane)]     = us16(fh);
            B0h[nxt * B0H + bidx16(50, lane) + 2] = us16(xv - fh);
        }
        __syncthreads();
    }

    // ===== Tail: G1(511) from B1[1] -> h1(511) =====
    {
        const int cur = (TLEN - 1) & 1;   // 1
        float d1[4][4];
#pragma unroll
        for (int nt = 0; nt < 4; nt++)
#pragma unroll
            for (int i2 = 0; i2 < 4; i2++) d1[nt][i2] = 0.f;
#pragma unroll
        for (int kt = 0; kt < KT1; kt++) {
            uint4 Ah = A1r[kt];
            uint4 Al = WA1[((w * KT1 + kt) * 2 + 1) * 32 + lane];
#pragma unroll
            for (int nt = 0; nt < 4; nt++) {
                uint4 bq = Bq1[cur * B1W + (kt * 4 + t4) * BPQ + nt * 8 + g4];
                mma_bf16(d1[nt], Ah.x, Ah.y, Ah.z, Ah.w, bq.x, bq.z);
                mma_bf16(d1[nt], Ah.x, Ah.y, Ah.z, Ah.w, bq.y, bq.w);
                mma_bf16(d1[nt], Al.x, Al.y, Al.z, Al.w, bq.x, bq.z);
            }
        }
#pragma unroll
        for (int nt = 0; nt < 4; nt++) {
            Gw[g4 * GP + nt * 8 + 2 * t4]           = d1[nt][0];
            Gw[g4 * GP + nt * 8 + 2 * t4 + 1]       = d1[nt][1];
            Gw[(g4 + 8) * GP + nt * 8 + 2 * t4]     = d1[nt][2];
            Gw[(g4 + 8) * GP + nt * 8 + 2 * t4 + 1] = d1[nt][3];
        }
        __syncwarp();
        float4 gv0 = *(float4*)(Gw + (4 * ul + 0) * GP + b4);
        float4 gv1 = *(float4*)(Gw + (4 * ul + 1) * GP + b4);
        float4 gv2 = *(float4*)(Gw + (4 * ul + 2) * GP + b4);
        float4 gv3 = *(float4*)(Gw + (4 * ul + 3) * GP + b4);
        __syncwarp();
        if (uok) {
            float* pi = (float*)&gv0; float* pf = (float*)&gv1;
            float* pg = (float*)&gv2; float* po = (float*)&gv3;
#pragma unroll
            for (int j = 0; j < 4; j++) {
                float ig = sigf(pi[j]), fg = sigf(pf[j]);
                float gg = tanha(pg[j]), og = sigf(po[j]);
                c1[j] = fmaf(fg, c1[j], ig * gg);
                h1v[j] = og * tanha(c1[j]);
            }
        }
    }
    __syncthreads();

    // ===== FC epilogue =====
    if (uok) {
        float fw = fc_w[uu];
#pragma unroll
        for (int j = 0; j < 4; j++) Gf[uu * 32 + b4 + j] = fw * h1v[j];
    }
    __syncthreads();
    if (tid < 32) {
        float s = fc_b[0];
#pragma unroll 10
        for (int k = 0; k < HDIM; k++) s += Gf[k * 32 + tid];
        out[b0g + tid] = s;
    }
}

extern "C" void kernel_launch(void* const* d_in, const int* in_sizes, int n_in,
                              void* d_out, int out_size) {
    const float* x     = (const float*)d_in[0];
    const float* w_ih0 = (const float*)d_in[1];
    const float* w_hh0 = (const float*)d_in[2];
    const float* b_ih0 = (const float*)d_in[3];
    const float* b_hh0 = (const float*)d_in[4];
    const float* w_ih1 = (const float*)d_in[5];
    const float* w_hh1 = (const float*)d_in[6];
    const float* b_ih1 = (const float*)d_in[7];
    const float* b_hh1 = (const float*)d_in[8];
    const float* fc_w  = (const float*)d_in[9];
    const float* fc_b  = (const float*)d_in[10];
    float* out = (float*)d_out;

    cudaFuncSetAttribute(lstm_kernel, cudaFuncAttributeMaxDynamicSharedMemorySize,
                         SMEM_BYTES);
    lstm_kernel<<<NCTA, NTH, SMEM_BYTES>>>(x, w_ih0, w_hh0, b_ih0, b_hh0,
                                           w_ih1, w_hh1, b_ih1, b_hh1,
                                           fc_w, fc_b, out);
}